// round 3
// baseline (speedup 1.0000x reference)
#include <cuda_runtime.h>
#include <cuda_bf16.h>

#define THREADS 256
#define PADT 65          // XsT row stride: bank(i1*65 + i2) = (i1+i2)%32

__global__ __launch_bounds__(THREADS)
void sym_equiv_kernel(const float* __restrict__ X,
                      const float* __restrict__ w,
                      float* __restrict__ out)
{
    __shared__ float XsT[64 * PADT];   // XsT[c][r] = X[r][c]  (16,640 B)
    __shared__ float Cvec[64];
    __shared__ float Tw[8], Dw[8];
    __shared__ float ws[15];

    const int t  = threadIdx.x;
    const int b  = blockIdx.x;
    const int i1 = t >> 2;             // row of X this thread owns
    const int ib = (t & 3) << 4;       // 16-col chunk start

    if (t < 15) ws[t] = w[t];

    // ---- Phase 1: coalesced float4 row load; transposed scalar stores;
    //      in-register reductions for R1(quad), T(warp), D(warp).
    const float* g = X + (size_t)b * 4096 + i1 * 64 + ib;
    float4 v0 = *(const float4*)(g + 0);
    float4 v1 = *(const float4*)(g + 4);
    float4 v2 = *(const float4*)(g + 8);
    float4 v3 = *(const float4*)(g + 12);

    // store X[i1][ib+k] -> XsT[ib+k][i1]   (2-way bank conflicts max)
    {
        float* s = XsT + ib * PADT + i1;
        s[0*PADT]=v0.x;  s[1*PADT]=v0.y;  s[2*PADT]=v0.z;  s[3*PADT]=v0.w;
        s[4*PADT]=v1.x;  s[5*PADT]=v1.y;  s[6*PADT]=v1.z;  s[7*PADT]=v1.w;
        s[8*PADT]=v2.x;  s[9*PADT]=v2.y;  s[10*PADT]=v2.z; s[11*PADT]=v2.w;
        s[12*PADT]=v3.x; s[13*PADT]=v3.y; s[14*PADT]=v3.z; s[15*PADT]=v3.w;
    }

    const float part = (v0.x + v0.y + v0.z + v0.w)
                     + (v1.x + v1.y + v1.z + v1.w)
                     + (v2.x + v2.y + v2.z + v2.w)
                     + (v3.x + v3.y + v3.z + v3.w);

    // r1 = full row sum, shared by all 4 quad lanes (width-4 xor reduce)
    float r1 = part;
    r1 += __shfl_xor_sync(0xffffffffu, r1, 1, 4);
    r1 += __shfl_xor_sync(0xffffffffu, r1, 2, 4);

    // Tw[warp] = sum of this warp's 8 row sums
    float ps = part;
    #pragma unroll
    for (int o = 16; o > 0; o >>= 1) ps += __shfl_xor_sync(0xffffffffu, ps, o);

    // dv = X[i1][i1] if this thread's chunk holds the diagonal, else 0
    const bool hold = (t & 3) == ((t >> 6) & 3);
    float dv = 0.f;
    {
        const int e = i1 & 15;
        if (e == 0)  dv = v0.x;  if (e == 1)  dv = v0.y;
        if (e == 2)  dv = v0.z;  if (e == 3)  dv = v0.w;
        if (e == 4)  dv = v1.x;  if (e == 5)  dv = v1.y;
        if (e == 6)  dv = v1.z;  if (e == 7)  dv = v1.w;
        if (e == 8)  dv = v2.x;  if (e == 9)  dv = v2.y;
        if (e == 10) dv = v2.z;  if (e == 11) dv = v2.w;
        if (e == 12) dv = v3.x;  if (e == 13) dv = v3.y;
        if (e == 14) dv = v3.z;  if (e == 15) dv = v3.w;
        if (!hold)   dv = 0.f;
    }
    float ds = dv;
    #pragma unroll
    for (int o = 16; o > 0; o >>= 1) ds += __shfl_xor_sync(0xffffffffu, ds, o);

    if ((t & 31) == 0) { Tw[t >> 5] = ps; Dw[t >> 5] = ds; }

    __syncthreads();                   // (1) XsT, Tw, Dw ready

    // ---- Phase 2: read transpose chunk ONCE; fold w8*X + w6*X^T into v;
    //      accumulate r2; build coefficients without further barriers.
    const float w8v = ws[8], w6v = ws[6];
    float r2 = 0.f;
    {
        const float* p = XsT + i1 * PADT + ib;   // XsT[i1][ib..] = X[ib..][i1]
        float a0, a1, a2, a3;
        a0=p[0];  a1=p[1];  a2=p[2];  a3=p[3];
        r2 += (a0+a1)+(a2+a3);
        v0.x=w8v*v0.x+w6v*a0; v0.y=w8v*v0.y+w6v*a1; v0.z=w8v*v0.z+w6v*a2; v0.w=w8v*v0.w+w6v*a3;
        a0=p[4];  a1=p[5];  a2=p[6];  a3=p[7];
        r2 += (a0+a1)+(a2+a3);
        v1.x=w8v*v1.x+w6v*a0; v1.y=w8v*v1.y+w6v*a1; v1.z=w8v*v1.z+w6v*a2; v1.w=w8v*v1.w+w6v*a3;
        a0=p[8];  a1=p[9];  a2=p[10]; a3=p[11];
        r2 += (a0+a1)+(a2+a3);
        v2.x=w8v*v2.x+w6v*a0; v2.y=w8v*v2.y+w6v*a1; v2.z=w8v*v2.z+w6v*a2; v2.w=w8v*v2.w+w6v*a3;
        a0=p[12]; a1=p[13]; a2=p[14]; a3=p[15];
        r2 += (a0+a1)+(a2+a3);
        v3.x=w8v*v3.x+w6v*a0; v3.y=w8v*v3.y+w6v*a1; v3.z=w8v*v3.z+w6v*a2; v3.w=w8v*v3.w+w6v*a3;
    }
    r2 += __shfl_xor_sync(0xffffffffu, r2, 1, 4);
    r2 += __shfl_xor_sync(0xffffffffu, r2, 2, 4);

    const float T = ((Tw[0]+Tw[1])+(Tw[2]+Tw[3])) + ((Tw[4]+Tw[5])+(Tw[6]+Tw[7]));
    const float D = ((Dw[0]+Dw[1])+(Dw[2]+Dw[3])) + ((Dw[4]+Dw[5])+(Dw[6]+Dw[7]));
    // xd = X[i1][i1], broadcast from the quad lane that holds it
    const float xd = __shfl_sync(0xffffffffu, dv, (i1 >> 4) & 3, 4);

    // per-partition weight folding (order of _set_partitions([0,1,2,3]))
    const float a  = ws[12]*r1 + ws[13]*r2 + ws[3]*xd + ws[14]*T + ws[4]*D;  // i1 + const
    const float ev = ws[5] *r1 + ws[9] *r2 + ws[0]*xd + ws[11]*T + ws[2]*D;  // diagonal
    if ((t & 3) == 0)
        Cvec[i1] = ws[7]*r1 + ws[10]*r2 + ws[1]*xd;                          // i2 terms

    __syncthreads();                   // (2) Cvec ready

    // ---- Phase 3: emit 16 outputs (float4-coalesced).
    float* orow = out + (size_t)b * 4096 + i1 * 64 + ib;
    const float4* c4p = (const float4*)(Cvec + ib);
    float4 vv[4] = {v0, v1, v2, v3};
    #pragma unroll
    for (int j = 0; j < 4; ++j) {
        const float4 c4 = c4p[j];
        float4 o;
        o.x = a + c4.x + vv[j].x;
        o.y = a + c4.y + vv[j].y;
        o.z = a + c4.z + vv[j].z;
        o.w = a + c4.w + vv[j].w;
        const int dd = i1 - (ib + j * 4);
        if (dd >= 0 && dd < 4) (&o.x)[dd] += ev;   // diagonal correction
        *(float4*)(orow + j * 4) = o;
    }
}

extern "C" void kernel_launch(void* const* d_in, const int* in_sizes, int n_in,
                              void* d_out, int out_size)
{
    const float* X = (const float*)d_in[0];      // (1024, 4096) fp32
    const float* w = (const float*)d_in[1];      // (15,) fp32
    // d_in[2] = B (15,4096,4096) — unused: W is fully determined by w via the
    // partition-structure decomposition (validated R0-R1, rel_err ~4e-7).
    float* out = (float*)d_out;                  // (1024, 4096) fp32
    (void)in_sizes; (void)n_in; (void)out_size;

    sym_equiv_kernel<<<1024, THREADS>>>(X, w, out);
}

// round 4
// speedup vs baseline: 1.4098x; 1.4098x over previous
#include <cuda_runtime.h>
#include <cuda_bf16.h>

#define PAD 65           // row-major pad: all smem access <=2-way conflicts
#define THREADS 256

__global__ __launch_bounds__(THREADS)
void sym_equiv_kernel(const float* __restrict__ X,
                      const float* __restrict__ w,
                      float* __restrict__ out)
{
    __shared__ float Xs[64 * PAD];     // Xs[r][c] = X[r][c]  (16,640 B)
    __shared__ float Cvec[64];
    __shared__ float Tw[8], Dw[8];
    __shared__ float ws[15];

    const int t  = threadIdx.x;
    const int b  = blockIdx.x;
    const int i1 = t >> 2;             // row this thread owns
    const int ib = (t & 3) << 4;       // 16-col chunk start

    if (t < 15) ws[t] = w[t];

    // ---- Phase 1: coalesced float4 row load -> regs + row-major smem,
    //      r1 via quad shuffles, per-warp T partial.
    const float* g = X + (size_t)b * 4096 + i1 * 64 + ib;
    float4 v0 = *(const float4*)(g + 0);
    float4 v1 = *(const float4*)(g + 4);
    float4 v2 = *(const float4*)(g + 8);
    float4 v3 = *(const float4*)(g + 12);

    float* srow = Xs + i1 * PAD + ib;
    srow[0]  = v0.x; srow[1]  = v0.y; srow[2]  = v0.z; srow[3]  = v0.w;
    srow[4]  = v1.x; srow[5]  = v1.y; srow[6]  = v1.z; srow[7]  = v1.w;
    srow[8]  = v2.x; srow[9]  = v2.y; srow[10] = v2.z; srow[11] = v2.w;
    srow[12] = v3.x; srow[13] = v3.y; srow[14] = v3.z; srow[15] = v3.w;

    const float part = (v0.x + v0.y + v0.z + v0.w)
                     + (v1.x + v1.y + v1.z + v1.w)
                     + (v2.x + v2.y + v2.z + v2.w)
                     + (v3.x + v3.y + v3.z + v3.w);
    float r1 = part;
    r1 += __shfl_xor_sync(0xffffffffu, r1, 1, 4);
    r1 += __shfl_xor_sync(0xffffffffu, r1, 2, 4);

    float ps = part;
    #pragma unroll
    for (int o = 16; o > 0; o >>= 1) ps += __shfl_xor_sync(0xffffffffu, ps, o);
    if ((t & 31) == 0) Tw[t >> 5] = ps;

    __syncthreads();                   // (1) Xs, Tw ready

    // ---- Phase 2: transpose reads ONCE; fold w8*X + w6*X^T into v while
    //      accumulating r2; xd via broadcast LDS; D via masked warp reduce.
    const float w8v = ws[8], w6v = ws[6];
    float r2;
    {
        const float* p = Xs + ib * PAD + i1;   // column i1, rows ib..ib+15
        float a0, a1, a2, a3, s0, s1;
        a0=p[0*PAD];  a1=p[1*PAD];  a2=p[2*PAD];  a3=p[3*PAD];
        s0 = (a0+a1)+(a2+a3);
        v0.x=w8v*v0.x+w6v*a0; v0.y=w8v*v0.y+w6v*a1; v0.z=w8v*v0.z+w6v*a2; v0.w=w8v*v0.w+w6v*a3;
        a0=p[4*PAD];  a1=p[5*PAD];  a2=p[6*PAD];  a3=p[7*PAD];
        s1 = (a0+a1)+(a2+a3);
        v1.x=w8v*v1.x+w6v*a0; v1.y=w8v*v1.y+w6v*a1; v1.z=w8v*v1.z+w6v*a2; v1.w=w8v*v1.w+w6v*a3;
        a0=p[8*PAD];  a1=p[9*PAD];  a2=p[10*PAD]; a3=p[11*PAD];
        s0 += (a0+a1)+(a2+a3);
        v2.x=w8v*v2.x+w6v*a0; v2.y=w8v*v2.y+w6v*a1; v2.z=w8v*v2.z+w6v*a2; v2.w=w8v*v2.w+w6v*a3;
        a0=p[12*PAD]; a1=p[13*PAD]; a2=p[14*PAD]; a3=p[15*PAD];
        s1 += (a0+a1)+(a2+a3);
        v3.x=w8v*v3.x+w6v*a0; v3.y=w8v*v3.y+w6v*a1; v3.z=w8v*v3.z+w6v*a2; v3.w=w8v*v3.w+w6v*a3;
        r2 = s0 + s1;
    }
    r2 += __shfl_xor_sync(0xffffffffu, r2, 1, 4);
    r2 += __shfl_xor_sync(0xffffffffu, r2, 2, 4);

    const float xd = Xs[i1 * (PAD + 1)];          // broadcast within quad

    float dq = ((t & 3) == 0) ? xd : 0.f;         // D = trace, per-warp partial
    #pragma unroll
    for (int o = 16; o > 0; o >>= 1) dq += __shfl_xor_sync(0xffffffffu, dq, o);
    if ((t & 31) == 0) Dw[t >> 5] = dq;

    // weight folding (partition map from _set_partitions([0,1,2,3]) order)
    const float a_part  = ws[12]*r1 + ws[13]*r2 + ws[3]*xd;   // i1-indexed
    const float ev_part = ws[5] *r1 + ws[9] *r2 + ws[0]*xd;   // diagonal
    if ((t & 3) == 0)
        Cvec[i1] = ws[7]*r1 + ws[10]*r2 + ws[1]*xd;           // i2-indexed

    __syncthreads();                   // (2) Cvec, Dw ready

    // ---- Phase 3: close coefficients with T, D; emit 16 outputs.
    const float T = ((Tw[0]+Tw[1])+(Tw[2]+Tw[3])) + ((Tw[4]+Tw[5])+(Tw[6]+Tw[7]));
    const float D = ((Dw[0]+Dw[1])+(Dw[2]+Dw[3])) + ((Dw[4]+Dw[5])+(Dw[6]+Dw[7]));
    const float a  = a_part  + ws[14]*T + ws[4]*D;
    const float ev = ev_part + ws[11]*T + ws[2]*D;

    float* orow = out + (size_t)b * 4096 + i1 * 64 + ib;
    const float4* c4p = (const float4*)(Cvec + ib);
    const float4 vv[4] = {v0, v1, v2, v3};
    #pragma unroll
    for (int j = 0; j < 4; ++j) {
        const float4 c4 = c4p[j];
        float4 o;
        o.x = a + c4.x + vv[j].x;
        o.y = a + c4.y + vv[j].y;
        o.z = a + c4.z + vv[j].z;
        o.w = a + c4.w + vv[j].w;
        const int dd = i1 - (ib + j * 4);
        if (dd >= 0 && dd < 4) (&o.x)[dd] += ev;   // diagonal correction
        *(float4*)(orow + j * 4) = o;
    }
}

extern "C" void kernel_launch(void* const* d_in, const int* in_sizes, int n_in,
                              void* d_out, int out_size)
{
    const float* X = (const float*)d_in[0];      // (1024, 4096) fp32
    const float* w = (const float*)d_in[1];      // (15,) fp32
    // d_in[2] = B (15,4096,4096) — unused: W is fully determined by w via the
    // partition-structure decomposition (validated R0-R2, rel_err ~4e-7).
    float* out = (float*)d_out;                  // (1024, 4096) fp32
    (void)in_sizes; (void)n_in; (void)out_size;

    sym_equiv_kernel<<<1024, THREADS>>>(X, w, out);
}

// round 5
// speedup vs baseline: 1.4128x; 1.0021x over previous
#include <cuda_runtime.h>
#include <cuda_bf16.h>

#define PAD 65           // bank(r*65+c) = (r+c)%32 -> transpose reads 2-way max
#define THREADS 512

__global__ __launch_bounds__(THREADS)
void sym_equiv_kernel(const float* __restrict__ X,
                      const float* __restrict__ w,
                      float* __restrict__ out)
{
    __shared__ float Xs[64 * PAD];     // 16,640 B
    __shared__ float Cvec[64];
    __shared__ __align__(16) float Tw[16];
    __shared__ __align__(16) float Dw[16];
    __shared__ float ws[15];

    const int t  = threadIdx.x;
    const int b  = blockIdx.x;
    const int i1 = t >> 3;             // row this thread owns
    const int ib = (t & 7) << 3;       // 8-col chunk start

    if (t < 15) ws[t] = w[t];

    // ---- Phase 1: coalesced float4 loads -> regs + row-major smem;
    //      r1 via width-8 shuffles; T partial per warp.
    const float* g = X + (size_t)b * 4096 + i1 * 64 + ib;
    float4 v0 = *(const float4*)(g + 0);
    float4 v1 = *(const float4*)(g + 4);

    float* srow = Xs + i1 * PAD + ib;
    srow[0] = v0.x; srow[1] = v0.y; srow[2] = v0.z; srow[3] = v0.w;
    srow[4] = v1.x; srow[5] = v1.y; srow[6] = v1.z; srow[7] = v1.w;

    const float part = (v0.x + v0.y) + (v0.z + v0.w)
                     + (v1.x + v1.y) + (v1.z + v1.w);
    float r1 = part;
    r1 += __shfl_xor_sync(0xffffffffu, r1, 1, 8);
    r1 += __shfl_xor_sync(0xffffffffu, r1, 2, 8);
    r1 += __shfl_xor_sync(0xffffffffu, r1, 4, 8);

    float ps = part;
    #pragma unroll
    for (int o = 16; o > 0; o >>= 1) ps += __shfl_xor_sync(0xffffffffu, ps, o);
    if ((t & 31) == 0) Tw[t >> 5] = ps;

    __syncthreads();                   // (1) Xs, Tw ready

    // ---- Phase 2: transpose chunk read ONCE, fused with w8/w6 fold and r2.
    const float w8v = ws[8], w6v = ws[6];
    float r2;
    {
        const float* p = Xs + ib * PAD + i1;    // column i1, rows ib..ib+7
        float a0, a1, a2, a3, s0;
        a0=p[0*PAD]; a1=p[1*PAD]; a2=p[2*PAD]; a3=p[3*PAD];
        s0 = (a0+a1)+(a2+a3);
        v0.x=w8v*v0.x+w6v*a0; v0.y=w8v*v0.y+w6v*a1; v0.z=w8v*v0.z+w6v*a2; v0.w=w8v*v0.w+w6v*a3;
        a0=p[4*PAD]; a1=p[5*PAD]; a2=p[6*PAD]; a3=p[7*PAD];
        r2 = s0 + (a0+a1)+(a2+a3);
        v1.x=w8v*v1.x+w6v*a0; v1.y=w8v*v1.y+w6v*a1; v1.z=w8v*v1.z+w6v*a2; v1.w=w8v*v1.w+w6v*a3;
    }
    r2 += __shfl_xor_sync(0xffffffffu, r2, 1, 8);
    r2 += __shfl_xor_sync(0xffffffffu, r2, 2, 8);
    r2 += __shfl_xor_sync(0xffffffffu, r2, 4, 8);

    const float xd = Xs[i1 * (PAD + 1)];          // broadcast within octet

    float dq = ((t & 7) == 0) ? xd : 0.f;         // trace partial per warp
    #pragma unroll
    for (int o = 16; o > 0; o >>= 1) dq += __shfl_xor_sync(0xffffffffu, dq, o);
    if ((t & 31) == 0) Dw[t >> 5] = dq;

    // weight folding (partition map from _set_partitions([0,1,2,3]) order)
    const float a_part  = ws[12]*r1 + ws[13]*r2 + ws[3]*xd;   // i1-indexed
    const float ev_part = ws[5] *r1 + ws[9] *r2 + ws[0]*xd;   // diagonal
    if ((t & 7) == 0)
        Cvec[i1] = ws[7]*r1 + ws[10]*r2 + ws[1]*xd;           // i2-indexed

    __syncthreads();                   // (2) Cvec, Dw ready

    // ---- Phase 3: close coefficients with T, D; emit 8 outputs.
    float T, D;
    {
        const float4* t4 = (const float4*)Tw;
        const float4* d4 = (const float4*)Dw;
        float4 x0 = t4[0], x1 = t4[1], x2 = t4[2], x3 = t4[3];
        T = ((x0.x+x0.y)+(x0.z+x0.w)) + ((x1.x+x1.y)+(x1.z+x1.w))
          + ((x2.x+x2.y)+(x2.z+x2.w)) + ((x3.x+x3.y)+(x3.z+x3.w));
        x0 = d4[0]; x1 = d4[1]; x2 = d4[2]; x3 = d4[3];
        D = ((x0.x+x0.y)+(x0.z+x0.w)) + ((x1.x+x1.y)+(x1.z+x1.w))
          + ((x2.x+x2.y)+(x2.z+x2.w)) + ((x3.x+x3.y)+(x3.z+x3.w));
    }
    const float a  = a_part  + ws[14]*T + ws[4]*D;
    const float ev = ev_part + ws[11]*T + ws[2]*D;

    float* orow = out + (size_t)b * 4096 + i1 * 64 + ib;
    const float4 c0 = ((const float4*)(Cvec + ib))[0];
    const float4 c1 = ((const float4*)(Cvec + ib))[1];
    float4 o0, o1;
    o0.x = a + c0.x + v0.x;  o0.y = a + c0.y + v0.y;
    o0.z = a + c0.z + v0.z;  o0.w = a + c0.w + v0.w;
    o1.x = a + c1.x + v1.x;  o1.y = a + c1.y + v1.y;
    o1.z = a + c1.z + v1.z;  o1.w = a + c1.w + v1.w;
    const int dd = i1 - ib;
    if (dd >= 0 && dd < 4)      (&o0.x)[dd]     += ev;   // diagonal correction
    else if (dd >= 4 && dd < 8) (&o1.x)[dd - 4] += ev;
    *(float4*)(orow + 0) = o0;
    *(float4*)(orow + 4) = o1;
}

extern "C" void kernel_launch(void* const* d_in, const int* in_sizes, int n_in,
                              void* d_out, int out_size)
{
    const float* X = (const float*)d_in[0];      // (1024, 4096) fp32
    const float* w = (const float*)d_in[1];      // (15,) fp32
    // d_in[2] = B (15,4096,4096) — unused: W is fully determined by w via the
    // partition-structure decomposition (validated R0-R3, rel_err ~4e-7).
    float* out = (float*)d_out;                  // (1024, 4096) fp32
    (void)in_sizes; (void)n_in; (void)out_size;

    sym_equiv_kernel<<<1024, THREADS>>>(X, w, out);
}

// round 6
// speedup vs baseline: 1.9359x; 1.3703x over previous
#include <cuda_runtime.h>
#include <cuda_bf16.h>

#define THREADS 256
#define PSTRIDE 33       // float2 row stride of P: bankpair(c*33+r) = (c+r)%16

__global__ __launch_bounds__(THREADS)
void sym_equiv_kernel(const float* __restrict__ X,
                      const float* __restrict__ w,
                      float* __restrict__ out)
{
    // P[c][r] = (X[r][c], X[r+32][c]),  c in [0,64), r in [0,32)
    __shared__ float2 P[64 * PSTRIDE];          // 16,896 B
    __shared__ float Cvec[64];
    __shared__ float Tw[8], Dw[8];
    __shared__ float ws[15];

    const int t  = threadIdx.x;
    const int b  = blockIdx.x;
    const int i1 = t >> 3;              // owns rows i1 and i1+32  (i1 in 0..31)
    const int q  = t & 7;
    const int ib = q << 2;              // owns cols [ib,ib+4) and [ib+32,ib+36)

    if (t < 15) ws[t] = w[t];

    // ---- Phase 1: 4 coalesced float4 loads; 8 paired STS.64; r1/T reductions.
    const float* base = X + (size_t)b * 4096;
    float4 va0 = *(const float4*)(base + i1 * 64 + ib);
    float4 va1 = *(const float4*)(base + i1 * 64 + ib + 32);
    float4 vb0 = *(const float4*)(base + (i1 + 32) * 64 + ib);
    float4 vb1 = *(const float4*)(base + (i1 + 32) * 64 + ib + 32);

    {
        float2* p0 = P + (size_t)ib * PSTRIDE + i1;          // cols ib..ib+3
        float2* p1 = P + (size_t)(ib + 32) * PSTRIDE + i1;   // cols ib+32..+35
        p0[0*PSTRIDE] = make_float2(va0.x, vb0.x);
        p0[1*PSTRIDE] = make_float2(va0.y, vb0.y);
        p0[2*PSTRIDE] = make_float2(va0.z, vb0.z);
        p0[3*PSTRIDE] = make_float2(va0.w, vb0.w);
        p1[0*PSTRIDE] = make_float2(va1.x, vb1.x);
        p1[1*PSTRIDE] = make_float2(va1.y, vb1.y);
        p1[2*PSTRIDE] = make_float2(va1.z, vb1.z);
        p1[3*PSTRIDE] = make_float2(va1.w, vb1.w);
    }

    const float pa = (va0.x + va0.y + va0.z + va0.w) + (va1.x + va1.y + va1.z + va1.w);
    const float pb = (vb0.x + vb0.y + vb0.z + vb0.w) + (vb1.x + vb1.y + vb1.z + vb1.w);
    float r1a = pa, r1b = pb;
    r1a += __shfl_xor_sync(0xffffffffu, r1a, 1, 8);
    r1a += __shfl_xor_sync(0xffffffffu, r1a, 2, 8);
    r1a += __shfl_xor_sync(0xffffffffu, r1a, 4, 8);
    r1b += __shfl_xor_sync(0xffffffffu, r1b, 1, 8);
    r1b += __shfl_xor_sync(0xffffffffu, r1b, 2, 8);
    r1b += __shfl_xor_sync(0xffffffffu, r1b, 4, 8);

    float ps = pa + pb;
    #pragma unroll
    for (int o = 16; o > 0; o >>= 1) ps += __shfl_xor_sync(0xffffffffu, ps, o);
    if ((t & 31) == 0) Tw[t >> 5] = ps;

    __syncthreads();                    // (1) P, Tw ready

    // ---- Phase 2: 8 LDS.64 transpose reads (every byte used), fused with
    //      the w8*X + w6*X^T fold and the column-sum (r2) partials.
    const float w8v = ws[8], w6v = ws[6];
    float r2a, r2b;
    {
        const float2* pa0 = P + (size_t)i1 * PSTRIDE + ib;        // col i1
        const float2* pb0 = P + (size_t)(i1 + 32) * PSTRIDE + ib; // col i1+32
        float2 q0 = pa0[0], q1 = pa0[1], q2 = pa0[2], q3 = pa0[3];
        r2a = ((q0.x + q1.x) + (q2.x + q3.x)) + ((q0.y + q1.y) + (q2.y + q3.y));
        va0.x = w8v*va0.x + w6v*q0.x;  va1.x = w8v*va1.x + w6v*q0.y;
        va0.y = w8v*va0.y + w6v*q1.x;  va1.y = w8v*va1.y + w6v*q1.y;
        va0.z = w8v*va0.z + w6v*q2.x;  va1.z = w8v*va1.z + w6v*q2.y;
        va0.w = w8v*va0.w + w6v*q3.x;  va1.w = w8v*va1.w + w6v*q3.y;
        q0 = pb0[0]; q1 = pb0[1]; q2 = pb0[2]; q3 = pb0[3];
        r2b = ((q0.x + q1.x) + (q2.x + q3.x)) + ((q0.y + q1.y) + (q2.y + q3.y));
        vb0.x = w8v*vb0.x + w6v*q0.x;  vb1.x = w8v*vb1.x + w6v*q0.y;
        vb0.y = w8v*vb0.y + w6v*q1.x;  vb1.y = w8v*vb1.y + w6v*q1.y;
        vb0.z = w8v*vb0.z + w6v*q2.x;  vb1.z = w8v*vb1.z + w6v*q2.y;
        vb0.w = w8v*vb0.w + w6v*q3.x;  vb1.w = w8v*vb1.w + w6v*q3.y;
    }
    // the 8 row-mates' chunks tile all 64 rows -> width-8 reduce = full column sums
    r2a += __shfl_xor_sync(0xffffffffu, r2a, 1, 8);
    r2a += __shfl_xor_sync(0xffffffffu, r2a, 2, 8);
    r2a += __shfl_xor_sync(0xffffffffu, r2a, 4, 8);
    r2b += __shfl_xor_sync(0xffffffffu, r2b, 1, 8);
    r2b += __shfl_xor_sync(0xffffffffu, r2b, 2, 8);
    r2b += __shfl_xor_sync(0xffffffffu, r2b, 4, 8);

    const float xa = P[(size_t)i1 * PSTRIDE + i1].x;          // X[i1][i1]
    const float xb = P[(size_t)(i1 + 32) * PSTRIDE + i1].y;   // X[i1+32][i1+32]

    float dq = (q == 0) ? (xa + xb) : 0.f;    // trace partial per warp
    #pragma unroll
    for (int o = 16; o > 0; o >>= 1) dq += __shfl_xor_sync(0xffffffffu, dq, o);
    if ((t & 31) == 0) Dw[t >> 5] = dq;

    // weight folding (partition map from _set_partitions([0,1,2,3]) order)
    const float aA  = ws[12]*r1a + ws[13]*r2a + ws[3]*xa;     // row i1
    const float eA  = ws[5] *r1a + ws[9] *r2a + ws[0]*xa;
    const float aB  = ws[12]*r1b + ws[13]*r2b + ws[3]*xb;     // row i1+32
    const float eB  = ws[5] *r1b + ws[9] *r2b + ws[0]*xb;
    if (q == 0) {
        Cvec[i1]      = ws[7]*r1a + ws[10]*r2a + ws[1]*xa;
        Cvec[i1 + 32] = ws[7]*r1b + ws[10]*r2b + ws[1]*xb;
    }

    __syncthreads();                    // (2) Cvec, Dw ready

    // ---- Phase 3: close with T, D; emit 16 outputs (4 STG.128).
    const float T = ((Tw[0]+Tw[1])+(Tw[2]+Tw[3])) + ((Tw[4]+Tw[5])+(Tw[6]+Tw[7]));
    const float D = ((Dw[0]+Dw[1])+(Dw[2]+Dw[3])) + ((Dw[4]+Dw[5])+(Dw[6]+Dw[7]));
    const float gT = ws[14]*T + ws[4]*D;       // constant part
    const float gE = ws[11]*T + ws[2]*D;       // diagonal constant part
    const float cA = aA + gT, cB = aB + gT;
    const float evA = eA + gE, evB = eB + gE;

    const float4 c0 = *(const float4*)(Cvec + ib);
    const float4 c1 = *(const float4*)(Cvec + ib + 32);

    float4 oA0, oA1, oB0, oB1;
    oA0.x = cA + c0.x + va0.x;  oA0.y = cA + c0.y + va0.y;
    oA0.z = cA + c0.z + va0.z;  oA0.w = cA + c0.w + va0.w;
    oA1.x = cA + c1.x + va1.x;  oA1.y = cA + c1.y + va1.y;
    oA1.z = cA + c1.z + va1.z;  oA1.w = cA + c1.w + va1.w;
    oB0.x = cB + c0.x + vb0.x;  oB0.y = cB + c0.y + vb0.y;
    oB0.z = cB + c0.z + vb0.z;  oB0.w = cB + c0.w + vb0.w;
    oB1.x = cB + c1.x + vb1.x;  oB1.y = cB + c1.y + vb1.y;
    oB1.z = cB + c1.z + vb1.z;  oB1.w = cB + c1.w + vb1.w;

    // diagonal corrections: row i1 diag col i1 (low half); row i1+32 diag
    // col i1+32 (high half). Both land in the thread with ib == (i1 & ~3).
    const int dd = i1 - ib;
    if (dd >= 0 && dd < 4) {
        (&oA0.x)[dd] += evA;
        (&oB1.x)[dd] += evB;
    }

    float* orow = out + (size_t)b * 4096;
    *(float4*)(orow + i1 * 64 + ib)            = oA0;
    *(float4*)(orow + i1 * 64 + ib + 32)       = oA1;
    *(float4*)(orow + (i1 + 32) * 64 + ib)      = oB0;
    *(float4*)(orow + (i1 + 32) * 64 + ib + 32) = oB1;
}

extern "C" void kernel_launch(void* const* d_in, const int* in_sizes, int n_in,
                              void* d_out, int out_size)
{
    const float* X = (const float*)d_in[0];      // (1024, 4096) fp32
    const float* w = (const float*)d_in[1];      // (15,) fp32
    // d_in[2] = B (15,4096,4096) — unused: W is fully determined by w via the
    // partition-structure decomposition (validated R0-R4, rel_err ~4e-7).
    float* out = (float*)d_out;                  // (1024, 4096) fp32
    (void)in_sizes; (void)n_in; (void)out_size;

    sym_equiv_kernel<<<1024, THREADS>>>(X, w, out);
}